// round 1
// baseline (speedup 1.0000x reference)
#include <cuda_runtime.h>
#include <cstdint>

#define M    100000
#define NQ   256
#define D    128
#define KNN  100
#define BB   4
#define TT   64
#define CAP  1024

// ---------------- device scratch (no allocs allowed) ----------------
static __device__ float g_qn[NQ];
static __device__ float g_tn[M];
static __device__ float g_dist[(size_t)NQ * M];                    // 102.4 MB
static __device__ int   g_idx[NQ * KNN];
static __device__ float g_emit[NQ * KNN];
static __device__ float g_states[(size_t)NQ * KNN * D];            // 13.1 MB
static __device__ float g_trans[(size_t)BB * (TT - 1) * KNN * KNN];// 10.1 MB

__device__ __forceinline__ unsigned int f2key(float f) {
    unsigned int u = __float_as_uint(f);
    return (u & 0x80000000u) ? ~u : (u | 0x80000000u);
}
__device__ __forceinline__ float key2f(unsigned int k) {
    unsigned int u = (k & 0x80000000u) ? (k & 0x7fffffffu) : ~k;
    return __uint_as_float(u);
}

// ---------------- norms ----------------
__global__ void norms_kernel(const float* __restrict__ Q, const float* __restrict__ Tg) {
    int i = blockIdx.x * blockDim.x + threadIdx.x;
    if (i < M) {
        const float4* p = (const float4*)(Tg + (size_t)i * D);
        float acc = 0.f;
#pragma unroll
        for (int k = 0; k < D / 4; k++) {
            float4 v = p[k];
            acc += v.x * v.x + v.y * v.y + v.z * v.z + v.w * v.w;
        }
        g_tn[i] = acc;
    } else if (i < M + NQ) {
        int q = i - M;
        const float4* p = (const float4*)(Q + (size_t)q * D);
        float acc = 0.f;
#pragma unroll
        for (int k = 0; k < D / 4; k++) {
            float4 v = p[k];
            acc += v.x * v.x + v.y * v.y + v.z * v.z + v.w * v.w;
        }
        g_qn[q] = acc;
    }
}

// ---------------- distance GEMM: d = qn + tn - 2*q.t ----------------
// 64x64 tile, 256 threads, 4x4 micro-tile, k-chunks of 16.
__global__ void dist_kernel(const float* __restrict__ Q, const float* __restrict__ Tg) {
    __shared__ __align__(16) float Qs[16][68];
    __shared__ __align__(16) float Ts[16][68];
    int tid = threadIdx.x;
    int tx = tid & 15, ty = tid >> 4;
    int q0 = blockIdx.y * 64, t0 = blockIdx.x * 64;
    int lr = tid >> 2;          // 0..63
    int lc = (tid & 3) << 2;    // 0,4,8,12
    float acc[4][4] = {};
    for (int k0 = 0; k0 < D; k0 += 16) {
        float4 qv = *(const float4*)&Q[(size_t)(q0 + lr) * D + k0 + lc];
        float4 tv = make_float4(0.f, 0.f, 0.f, 0.f);
        int trow = t0 + lr;
        if (trow < M) tv = *(const float4*)&Tg[(size_t)trow * D + k0 + lc];
        Qs[lc + 0][lr] = qv.x; Qs[lc + 1][lr] = qv.y;
        Qs[lc + 2][lr] = qv.z; Qs[lc + 3][lr] = qv.w;
        Ts[lc + 0][lr] = tv.x; Ts[lc + 1][lr] = tv.y;
        Ts[lc + 2][lr] = tv.z; Ts[lc + 3][lr] = tv.w;
        __syncthreads();
#pragma unroll
        for (int k = 0; k < 16; k++) {
            float4 a  = *(const float4*)&Qs[k][ty * 4];
            float4 b4 = *(const float4*)&Ts[k][tx * 4];
            acc[0][0] += a.x * b4.x; acc[0][1] += a.x * b4.y; acc[0][2] += a.x * b4.z; acc[0][3] += a.x * b4.w;
            acc[1][0] += a.y * b4.x; acc[1][1] += a.y * b4.y; acc[1][2] += a.y * b4.z; acc[1][3] += a.y * b4.w;
            acc[2][0] += a.z * b4.x; acc[2][1] += a.z * b4.y; acc[2][2] += a.z * b4.z; acc[2][3] += a.z * b4.w;
            acc[3][0] += a.w * b4.x; acc[3][1] += a.w * b4.y; acc[3][2] += a.w * b4.z; acc[3][3] += a.w * b4.w;
        }
        __syncthreads();
    }
#pragma unroll
    for (int ii = 0; ii < 4; ii++) {
        int q = q0 + ty * 4 + ii;
        float qn = g_qn[q];
#pragma unroll
        for (int jj = 0; jj < 4; jj++) {
            int t = t0 + tx * 4 + jj;
            if (t < M) g_dist[(size_t)q * M + t] = qn + g_tn[t] - 2.f * acc[ii][jj];
        }
    }
}

// ---------------- exact top-K selection (radix-select + bitonic) ----------------
__global__ void select_kernel() {
    int q = blockIdx.x;
    const float* drow = g_dist + (size_t)q * M;
    __shared__ unsigned int hist[2048];
    __shared__ unsigned int scanbuf[256];
    __shared__ unsigned int s_prefix;
    __shared__ int s_kneed;
    __shared__ unsigned int s_cnt;
    __shared__ unsigned long long buf[CAP];
    __shared__ float sred[256];
    __shared__ float s_dmin;
    int tid = threadIdx.x;
    if (tid == 0) { s_prefix = 0u; s_kneed = KNN; s_cnt = 0u; }
    __syncthreads();

    const int shifts[3]  = {21, 10, 0};
    const int bitsArr[3] = {11, 11, 10};
    for (int p = 0; p < 3; p++) {
        int shift = shifts[p];
        int nb = 1 << bitsArr[p];
        for (int i = tid; i < nb; i += 256) hist[i] = 0u;
        __syncthreads();
        unsigned int prefix = s_prefix;
        int top = shift + bitsArr[p];
        for (int j = tid; j < M; j += 256) {
            unsigned int key = f2key(drow[j]);
            bool ok = (top >= 32) || ((key >> top) == (prefix >> top));
            if (ok) {
                unsigned int bin = (key >> shift) & (unsigned int)(nb - 1);
                unsigned int mm = __match_any_sync(__activemask(), bin);
                if ((int)(tid & 31) == __ffs(mm) - 1) atomicAdd(&hist[bin], (unsigned)__popc(mm));
            }
        }
        __syncthreads();
        int chunk = nb / 256;
        unsigned int ssum = 0u;
        for (int i = 0; i < chunk; i++) ssum += hist[tid * chunk + i];
        scanbuf[tid] = ssum;
        __syncthreads();
        for (int off = 1; off < 256; off <<= 1) {
            unsigned int a = scanbuf[tid];
            unsigned int b = (tid >= off) ? scanbuf[tid - off] : 0u;
            __syncthreads();
            scanbuf[tid] = a + b;
            __syncthreads();
        }
        int kneed = s_kneed;
        unsigned int excl = (tid == 0) ? 0u : scanbuf[tid - 1];
        unsigned int incl = scanbuf[tid];
        __syncthreads();  // snapshot kneed before anyone rewrites it
        if ((int)excl < kneed && kneed <= (int)incl) {
            unsigned int c = excl;
            for (int i = 0; i < chunk; i++) {
                unsigned int h = hist[tid * chunk + i];
                c += h;
                if (kneed <= (int)c) {
                    s_prefix = prefix | ((unsigned int)(tid * chunk + i) << shift);
                    s_kneed = kneed - (int)(c - h);
                    break;
                }
            }
        }
        __syncthreads();
    }

    unsigned int tk = s_prefix;  // key of 100th smallest
    for (int j = tid; j < M; j += 256) {
        unsigned int key = f2key(drow[j]);
        if (key <= tk) {
            unsigned int pos = atomicAdd(&s_cnt, 1u);
            if (pos < CAP) buf[pos] = ((unsigned long long)key << 32) | (unsigned int)j;
        }
    }
    __syncthreads();
    unsigned int n = s_cnt; if (n > CAP) n = CAP;
    for (int i = tid; i < CAP; i += 256)
        if (i >= (int)n) buf[i] = 0xFFFFFFFFFFFFFFFFull;
    __syncthreads();

    // bitonic sort CAP entries ascending (key, then idx — packed in u64)
    for (unsigned int k2 = 2; k2 <= CAP; k2 <<= 1) {
        for (unsigned int j2 = k2 >> 1; j2 > 0; j2 >>= 1) {
            for (int i = tid; i < CAP; i += 256) {
                int l = i ^ (int)j2;
                if (l > i) {
                    unsigned long long a = buf[i], b = buf[l];
                    bool up = ((i & (int)k2) == 0);
                    if ((a > b) == up) { buf[i] = b; buf[l] = a; }
                }
            }
            __syncthreads();
        }
    }

    if (tid == 0) s_dmin = key2f((unsigned int)(buf[0] >> 32));
    __syncthreads();
    float dmin = s_dmin;
    float myex = 0.f; int myidx = 0;
    if (tid < KNN) {
        unsigned long long e = buf[tid];
        myidx = (int)(unsigned int)(e & 0xffffffffull);
        float d = key2f((unsigned int)(e >> 32));
        myex = expf(dmin - d);   // softmax(-d) numerator with max subtracted
    }
    sred[tid] = (tid < KNN) ? myex : 0.f;
    __syncthreads();
    for (int off = 128; off > 0; off >>= 1) {
        if (tid < off) sred[tid] += sred[tid + off];
        __syncthreads();
    }
    float ssum = sred[0];
    if (tid < KNN) {
        g_emit[q * KNN + tid] = myex / ssum;
        g_idx[q * KNN + tid] = myidx;
    }
}

// ---------------- states gather ----------------
__global__ void gather_states_kernel(const float* __restrict__ Tg) {
    int n = blockIdx.x * blockDim.x + threadIdx.x;  // float4 index
    if (n >= NQ * KNN * (D / 4)) return;
    int row = n / (D / 4);
    int c = n % (D / 4);
    int tgt = g_idx[row];
    float4 v = *(const float4*)&Tg[(size_t)tgt * D + c * 4];
    *(float4*)&g_states[(size_t)row * D + c * 4] = v;
}

// ---------------- transitions: exp(-||a_i - b_j||^2) ----------------
__global__ void trans_kernel() {
    extern __shared__ __align__(16) float s[];
    float* sA = s;                 // [128][100] (k-major)
    float* sB = s + D * KNN;
    float* an = s + 2 * D * KNN;   // [100]
    float* bn = an + KNN;
    int bt = blockIdx.x;
    int b = bt / (TT - 1), tl = bt % (TT - 1);
    int qA = b * TT + tl, qB = qA + 1;
    for (int n = threadIdx.x; n < KNN * D; n += blockDim.x) {
        int i = n / D, k = n % D;
        sA[k * KNN + i] = g_states[(size_t)qA * KNN * D + n];
        sB[k * KNN + i] = g_states[(size_t)qB * KNN * D + n];
    }
    __syncthreads();
    for (int i = threadIdx.x; i < 2 * KNN; i += blockDim.x) {
        int ii = (i < KNN) ? i : (i - KNN);
        const float* sp = (i < KNN) ? sA : sB;
        float acc = 0.f;
        for (int k = 0; k < D; k++) { float x = sp[k * KNN + ii]; acc += x * x; }
        if (i < KNN) an[ii] = acc; else bn[ii] = acc;
    }
    __syncthreads();
    float* trow = g_trans + (size_t)bt * KNN * KNN;
    for (int t4 = threadIdx.x; t4 < 625; t4 += blockDim.x) {
        int i0 = (t4 / 25) * 4, j0 = (t4 % 25) * 4;
        float acc[4][4] = {};
        for (int k = 0; k < D; k++) {
            float4 a  = *(const float4*)&sA[k * KNN + i0];
            float4 b4 = *(const float4*)&sB[k * KNN + j0];
            acc[0][0] += a.x * b4.x; acc[0][1] += a.x * b4.y; acc[0][2] += a.x * b4.z; acc[0][3] += a.x * b4.w;
            acc[1][0] += a.y * b4.x; acc[1][1] += a.y * b4.y; acc[1][2] += a.y * b4.z; acc[1][3] += a.y * b4.w;
            acc[2][0] += a.z * b4.x; acc[2][1] += a.z * b4.y; acc[2][2] += a.z * b4.z; acc[2][3] += a.z * b4.w;
            acc[3][0] += a.w * b4.x; acc[3][1] += a.w * b4.y; acc[3][2] += a.w * b4.z; acc[3][3] += a.w * b4.w;
        }
#pragma unroll
        for (int ii = 0; ii < 4; ii++)
#pragma unroll
            for (int jj = 0; jj < 4; jj++) {
                int i = i0 + ii, j = j0 + jj;
                float dd = an[i] + bn[j] - 2.f * acc[ii][jj];
                trow[i * KNN + j] = expf(-dd);
            }
    }
}

// ---------------- viterbi + backtrack + output gather ----------------
__global__ void viterbi_kernel(const float* __restrict__ Tg, float* __restrict__ out) {
    int b = blockIdx.x;
    int tid = threadIdx.x;  // 128
    __shared__ float v[128], vn[128], red[128];
    __shared__ unsigned char bp[TT - 1][KNN];
    __shared__ int path[TT];
    v[tid] = (tid < KNN) ? g_emit[(b * TT + 0) * KNN + tid] : 0.f;
    __syncthreads();
    for (int t = 1; t < TT; t++) {
        const float* tr = g_trans + (size_t)(b * (TT - 1) + (t - 1)) * KNN * KNN;
        float best = 0.f; int back = 0;
        if (tid < KNN) {
            best = v[0] * tr[tid];
            for (int i = 1; i < KNN; i++) {
                float sc = v[i] * tr[i * KNN + tid];
                if (sc > best) { best = sc; back = i; }  // strict > keeps first max
            }
            bp[t - 1][tid] = (unsigned char)back;
        }
        float em = (tid < KNN) ? g_emit[(b * TT + t) * KNN + tid] : 0.f;
        vn[tid] = (tid < KNN) ? best * em : 0.f;
        red[tid] = vn[tid];
        __syncthreads();
        for (int off = 64; off > 0; off >>= 1) {
            if (tid < off) red[tid] = fmaxf(red[tid], red[tid + off]);
            __syncthreads();
        }
        float m = fmaxf(red[0], 1e-30f);
        __syncthreads();
        v[tid] = vn[tid] / m;
        __syncthreads();
    }
    if (tid == 0) {
        float bv = v[0]; int last = 0;
        for (int j = 1; j < KNN; j++) if (v[j] > bv) { bv = v[j]; last = j; }
        path[TT - 1] = last;
        int idx = last;
        for (int t = TT - 2; t >= 0; t--) { idx = bp[t][idx]; path[t] = idx; }
    }
    __syncthreads();
    for (int n = tid; n < TT * D; n += 128) {
        int t = n / D, d2 = n % D;
        int row = g_idx[(b * TT + t) * KNN + path[t]];
        out[(size_t)(b * TT + t) * D + d2] = Tg[(size_t)row * D + d2];
    }
}

// ---------------- launch ----------------
extern "C" void kernel_launch(void* const* d_in, const int* in_sizes, int n_in,
                              void* d_out, int out_size) {
    (void)in_sizes; (void)n_in; (void)out_size;
    const float* Q  = (const float*)d_in[0];
    const float* Tg = (const float*)d_in[1];
    float* out = (float*)d_out;

    const int trans_smem = (2 * D * KNN + 2 * KNN) * (int)sizeof(float);  // 103200 B
    cudaFuncSetAttribute(trans_kernel, cudaFuncAttributeMaxDynamicSharedMemorySize, trans_smem);

    norms_kernel<<<(M + NQ + 255) / 256, 256>>>(Q, Tg);
    dist_kernel<<<dim3((M + 63) / 64, NQ / 64), 256>>>(Q, Tg);
    select_kernel<<<NQ, 256>>>();
    gather_states_kernel<<<(NQ * KNN * (D / 4) + 255) / 256, 256>>>(Tg);
    trans_kernel<<<BB * (TT - 1), 256, trans_smem>>>();
    viterbi_kernel<<<BB, 128>>>(Tg, out);
}

// round 2
// speedup vs baseline: 1.5931x; 1.5931x over previous
#include <cuda_runtime.h>
#include <cstdint>

#define M    100000
#define NQ   256
#define D    128
#define KNN  100
#define BB   4
#define TT   64
#define CAP2 16384   // u64 candidate capacity in select (131072 B smem)

// ---------------- device scratch (no allocs allowed) ----------------
static __device__ float        g_qn[NQ];
static __device__ float        g_tn[M];
static __device__ unsigned int g_key[(size_t)NQ * M];               // 102.4 MB sortable keys
static __device__ int          g_idx[NQ * KNN];
static __device__ float        g_emit[NQ * KNN];
static __device__ float        g_states[(size_t)NQ * KNN * D];
static __device__ float        g_trans[(size_t)BB * (TT - 1) * KNN * KNN];

__device__ __forceinline__ unsigned int f2key(float f) {
    unsigned int u = __float_as_uint(f);
    return (u & 0x80000000u) ? ~u : (u | 0x80000000u);
}
__device__ __forceinline__ float key2f(unsigned int k) {
    unsigned int u = (k & 0x80000000u) ? (k & 0x7fffffffu) : ~k;
    return __uint_as_float(u);
}

// ---------------- norms ----------------
__global__ void norms_kernel(const float* __restrict__ Q, const float* __restrict__ Tg) {
    int i = blockIdx.x * blockDim.x + threadIdx.x;
    if (i < M) {
        const float4* p = (const float4*)(Tg + (size_t)i * D);
        float acc = 0.f;
#pragma unroll
        for (int k = 0; k < D / 4; k++) {
            float4 v = p[k];
            acc += v.x * v.x + v.y * v.y + v.z * v.z + v.w * v.w;
        }
        g_tn[i] = acc;
    } else if (i < M + NQ) {
        int q = i - M;
        const float4* p = (const float4*)(Q + (size_t)q * D);
        float acc = 0.f;
#pragma unroll
        for (int k = 0; k < D / 4; k++) {
            float4 v = p[k];
            acc += v.x * v.x + v.y * v.y + v.z * v.z + v.w * v.w;
        }
        g_qn[q] = acc;
    }
}

// ---------------- distance GEMM -> sortable keys ----------------
// 128(q) x 128(t) tile, 256 threads, 8x8 microtile, k-chunks of 16.
__global__ __launch_bounds__(256, 2)
void dist_kernel(const float* __restrict__ Q, const float* __restrict__ Tg) {
    __shared__ __align__(16) float Qs[16][132];
    __shared__ __align__(16) float Ts[16][132];
    int tid = threadIdx.x;
    int tx = tid & 15, ty = tid >> 4;
    int q0 = blockIdx.y * 128, t0 = blockIdx.x * 128;
    int lr = tid >> 1;          // 0..127
    int lc = (tid & 1) * 8;     // 0 or 8
    const float* qbase = Q + (size_t)(q0 + lr) * D + lc;
    bool tvalid = (t0 + lr) < M;
    const float* tbase = Tg + (size_t)(tvalid ? (t0 + lr) : 0) * D + lc;

    float acc[8][8] = {};
    for (int k0 = 0; k0 < D; k0 += 16) {
        float4 qa = *(const float4*)(qbase + k0);
        float4 qb = *(const float4*)(qbase + k0 + 4);
        float4 ta = make_float4(0.f, 0.f, 0.f, 0.f), tb = ta;
        if (tvalid) {
            ta = *(const float4*)(tbase + k0);
            tb = *(const float4*)(tbase + k0 + 4);
        }
        Qs[lc + 0][lr] = qa.x; Qs[lc + 1][lr] = qa.y; Qs[lc + 2][lr] = qa.z; Qs[lc + 3][lr] = qa.w;
        Qs[lc + 4][lr] = qb.x; Qs[lc + 5][lr] = qb.y; Qs[lc + 6][lr] = qb.z; Qs[lc + 7][lr] = qb.w;
        Ts[lc + 0][lr] = ta.x; Ts[lc + 1][lr] = ta.y; Ts[lc + 2][lr] = ta.z; Ts[lc + 3][lr] = ta.w;
        Ts[lc + 4][lr] = tb.x; Ts[lc + 5][lr] = tb.y; Ts[lc + 6][lr] = tb.z; Ts[lc + 7][lr] = tb.w;
        __syncthreads();
#pragma unroll
        for (int k = 0; k < 16; k++) {
            float4 a0 = *(const float4*)&Qs[k][ty * 8];
            float4 a1 = *(const float4*)&Qs[k][ty * 8 + 4];
            float4 b0 = *(const float4*)&Ts[k][tx * 8];
            float4 b1 = *(const float4*)&Ts[k][tx * 8 + 4];
            float av[8] = {a0.x, a0.y, a0.z, a0.w, a1.x, a1.y, a1.z, a1.w};
            float bv[8] = {b0.x, b0.y, b0.z, b0.w, b1.x, b1.y, b1.z, b1.w};
#pragma unroll
            for (int ii = 0; ii < 8; ii++)
#pragma unroll
                for (int jj = 0; jj < 8; jj++)
                    acc[ii][jj] += av[ii] * bv[jj];
        }
        __syncthreads();
    }

    // epilogue: coalesced uint4 key stores
    int tcol = t0 + tx * 8;
    float tn[8];
    bool v0 = (tcol + 3) < M, v1 = (tcol + 7) < M;
#pragma unroll
    for (int jj = 0; jj < 8; jj++)
        tn[jj] = ((jj < 4) ? v0 : v1) ? g_tn[tcol + jj] : 0.f;
#pragma unroll
    for (int ii = 0; ii < 8; ii++) {
        int q = q0 + ty * 8 + ii;
        float qn = g_qn[q];
        unsigned int keys[8];
#pragma unroll
        for (int jj = 0; jj < 8; jj++) {
            float s = qn + tn[jj];
            keys[jj] = f2key(s - 2.f * acc[ii][jj]);
        }
        unsigned int* dst = g_key + (size_t)q * M + tcol;
        if (v0) *(uint4*)dst = make_uint4(keys[0], keys[1], keys[2], keys[3]);
        if (v1) *(uint4*)(dst + 4) = make_uint4(keys[4], keys[5], keys[6], keys[7]);
    }
}

// ---------------- exact top-K: 16-bit histogram + collect + bitonic ----------------
__global__ void select_kernel() {
    extern __shared__ __align__(16) unsigned int sm[];   // 32768 u32 = 131072 B
    unsigned int* hist = sm;                              // phase 1: 65536 u16 packed
    unsigned long long* buf = (unsigned long long*)sm;    // phase 2: CAP2 u64 (reuse)
    __shared__ unsigned int scanbuf[256];
    __shared__ unsigned int h256[256];
    __shared__ unsigned int s_prefix, s_cnt;
    __shared__ int s_nless, s_cntbin, s_sub;
    __shared__ float s_dmin;
    __shared__ float sred[256];

    int q = blockIdx.x;
    int tid = threadIdx.x;
    const unsigned int* krow = g_key + (size_t)q * M;

    for (int i = tid; i < 32768; i += 256) hist[i] = 0u;
    if (tid == 0) { s_cnt = 0u; s_sub = 256; }
    __syncthreads();

    // pass 1: histogram of key high 16 bits (u16 counters packed 2-per-u32)
    for (int j = tid; j < M; j += 256) {
        unsigned int bin = krow[j] >> 16;
        atomicAdd(&hist[bin >> 1], 1u << ((bin & 1u) * 16));
    }
    __syncthreads();

    // per-thread partial sums over 256 bins (= 128 words)
    unsigned int ssum = 0u;
    for (int w = 0; w < 128; w++) {
        unsigned int v = hist[tid * 128 + w];
        ssum += (v & 0xffffu) + (v >> 16);
    }
    scanbuf[tid] = ssum;
    __syncthreads();
    for (int off = 1; off < 256; off <<= 1) {
        unsigned int a = scanbuf[tid];
        unsigned int b = (tid >= off) ? scanbuf[tid - off] : 0u;
        __syncthreads();
        scanbuf[tid] = a + b;
        __syncthreads();
    }
    unsigned int excl = (tid == 0) ? 0u : scanbuf[tid - 1];
    unsigned int incl = scanbuf[tid];
    if (excl < KNN && KNN <= (int)incl) {
        unsigned int c = excl;
        for (int w = 0; w < 128; w++) {
            unsigned int v = hist[tid * 128 + w];
            unsigned int lo = v & 0xffffu;
            if (KNN <= (int)(c + lo)) {
                s_prefix = (unsigned int)(tid * 256 + 2 * w);
                s_nless = (int)c; s_cntbin = (int)lo; break;
            }
            c += lo;
            unsigned int hi = v >> 16;
            if (KNN <= (int)(c + hi)) {
                s_prefix = (unsigned int)(tid * 256 + 2 * w + 1);
                s_nless = (int)c; s_cntbin = (int)hi; break;
            }
            c += hi;
        }
    }
    __syncthreads();
    unsigned int pfx = s_prefix;
    int nless = s_nless, cntbin = s_cntbin;

    // rare exact refine if the candidate set would overflow CAP2
    if (nless + cntbin > CAP2 - 64) {
        for (int i = tid; i < 256; i += 256) h256[i] = 0u;
        __syncthreads();
        for (int j = tid; j < M; j += 256) {
            unsigned int key = krow[j];
            if ((key >> 16) == pfx) atomicAdd(&h256[(key >> 8) & 255u], 1u);
        }
        __syncthreads();
        if (tid == 0) {
            int c = nless;
            for (int b = 0; b < 256; b++) {
                c += (int)h256[b];
                if (KNN <= c) { s_sub = b; break; }
            }
        }
        __syncthreads();
    }
    int sub = s_sub;

    // pass 2: collect all candidates <= threshold bin
    for (int j = tid; j < M; j += 256) {
        unsigned int key = krow[j];
        unsigned int hi = key >> 16;
        bool take = (hi < pfx) ||
                    (hi == pfx && (sub >= 256 || (int)((key >> 8) & 255u) <= sub));
        if (take) {
            unsigned int pos = atomicAdd(&s_cnt, 1u);
            if (pos < CAP2)
                buf[pos] = ((unsigned long long)key << 32) | (unsigned int)j;
        }
    }
    __syncthreads();
    int n = (int)s_cnt; if (n > CAP2) n = CAP2;
    int size = 1024;
    while (size < n) size <<= 1;
    for (int i = tid; i < size; i += 256)
        if (i >= n) buf[i] = 0xFFFFFFFFFFFFFFFFull;
    __syncthreads();

    // bitonic sort ascending on packed (key, idx)
    for (int k2 = 2; k2 <= size; k2 <<= 1) {
        for (int j2 = k2 >> 1; j2 > 0; j2 >>= 1) {
            for (int i = tid; i < size; i += 256) {
                int l = i ^ j2;
                if (l > i) {
                    unsigned long long a = buf[i], b = buf[l];
                    bool up = ((i & k2) == 0);
                    if ((a > b) == up) { buf[i] = b; buf[l] = a; }
                }
            }
            __syncthreads();
        }
    }

    if (tid == 0) s_dmin = key2f((unsigned int)(buf[0] >> 32));
    __syncthreads();
    float dmin = s_dmin;
    float myex = 0.f; int myidx = 0;
    if (tid < KNN) {
        unsigned long long e = buf[tid];
        myidx = (int)(unsigned int)(e & 0xffffffffull);
        float d = key2f((unsigned int)(e >> 32));
        myex = expf(dmin - d);
    }
    sred[tid] = (tid < KNN) ? myex : 0.f;
    __syncthreads();
    for (int off = 128; off > 0; off >>= 1) {
        if (tid < off) sred[tid] += sred[tid + off];
        __syncthreads();
    }
    float ssum2 = sred[0];
    if (tid < KNN) {
        g_emit[q * KNN + tid] = myex / ssum2;
        g_idx[q * KNN + tid] = myidx;
    }
}

// ---------------- states gather ----------------
__global__ void gather_states_kernel(const float* __restrict__ Tg) {
    int n = blockIdx.x * blockDim.x + threadIdx.x;
    if (n >= NQ * KNN * (D / 4)) return;
    int row = n / (D / 4);
    int c = n % (D / 4);
    int tgt = g_idx[row];
    float4 v = *(const float4*)&Tg[(size_t)tgt * D + c * 4];
    *(float4*)&g_states[(size_t)row * D + c * 4] = v;
}

// ---------------- transitions: exp(-||a_i - b_j||^2) ----------------
__global__ void trans_kernel() {
    extern __shared__ __align__(16) float s[];
    float* sA = s;
    float* sB = s + D * KNN;
    float* an = s + 2 * D * KNN;
    float* bn = an + KNN;
    int bt = blockIdx.x;
    int b = bt / (TT - 1), tl = bt % (TT - 1);
    int qA = b * TT + tl, qB = qA + 1;
    for (int n = threadIdx.x; n < KNN * D; n += blockDim.x) {
        int i = n / D, k = n % D;
        sA[k * KNN + i] = g_states[(size_t)qA * KNN * D + n];
        sB[k * KNN + i] = g_states[(size_t)qB * KNN * D + n];
    }
    __syncthreads();
    for (int i = threadIdx.x; i < 2 * KNN; i += blockDim.x) {
        int ii = (i < KNN) ? i : (i - KNN);
        const float* sp = (i < KNN) ? sA : sB;
        float acc = 0.f;
        for (int k = 0; k < D; k++) { float x = sp[k * KNN + ii]; acc += x * x; }
        if (i < KNN) an[ii] = acc; else bn[ii] = acc;
    }
    __syncthreads();
    float* trow = g_trans + (size_t)bt * KNN * KNN;
    for (int t4 = threadIdx.x; t4 < 625; t4 += blockDim.x) {
        int i0 = (t4 / 25) * 4, j0 = (t4 % 25) * 4;
        float acc[4][4] = {};
        for (int k = 0; k < D; k++) {
            float4 a  = *(const float4*)&sA[k * KNN + i0];
            float4 b4 = *(const float4*)&sB[k * KNN + j0];
            acc[0][0] += a.x * b4.x; acc[0][1] += a.x * b4.y; acc[0][2] += a.x * b4.z; acc[0][3] += a.x * b4.w;
            acc[1][0] += a.y * b4.x; acc[1][1] += a.y * b4.y; acc[1][2] += a.y * b4.z; acc[1][3] += a.y * b4.w;
            acc[2][0] += a.z * b4.x; acc[2][1] += a.z * b4.y; acc[2][2] += a.z * b4.z; acc[2][3] += a.z * b4.w;
            acc[3][0] += a.w * b4.x; acc[3][1] += a.w * b4.y; acc[3][2] += a.w * b4.z; acc[3][3] += a.w * b4.w;
        }
#pragma unroll
        for (int ii = 0; ii < 4; ii++)
#pragma unroll
            for (int jj = 0; jj < 4; jj++) {
                int i = i0 + ii, j = j0 + jj;
                float dd = an[i] + bn[j] - 2.f * acc[ii][jj];
                trow[i * KNN + j] = expf(-dd);
            }
    }
}

// ---------------- viterbi + backtrack + output gather ----------------
__global__ void viterbi_kernel(const float* __restrict__ Tg, float* __restrict__ out) {
    int b = blockIdx.x;
    int tid = threadIdx.x;  // 128
    __shared__ float v[128], vn[128], red[128];
    __shared__ unsigned char bp[TT - 1][KNN];
    __shared__ int path[TT];
    v[tid] = (tid < KNN) ? g_emit[(b * TT + 0) * KNN + tid] : 0.f;
    __syncthreads();
    for (int t = 1; t < TT; t++) {
        const float* tr = g_trans + (size_t)(b * (TT - 1) + (t - 1)) * KNN * KNN;
        float best = 0.f; int back = 0;
        if (tid < KNN) {
            best = v[0] * tr[tid];
            for (int i = 1; i < KNN; i++) {
                float sc = v[i] * tr[i * KNN + tid];
                if (sc > best) { best = sc; back = i; }
            }
            bp[t - 1][tid] = (unsigned char)back;
        }
        float em = (tid < KNN) ? g_emit[(b * TT + t) * KNN + tid] : 0.f;
        vn[tid] = (tid < KNN) ? best * em : 0.f;
        red[tid] = vn[tid];
        __syncthreads();
        for (int off = 64; off > 0; off >>= 1) {
            if (tid < off) red[tid] = fmaxf(red[tid], red[tid + off]);
            __syncthreads();
        }
        float m = fmaxf(red[0], 1e-30f);
        __syncthreads();
        v[tid] = vn[tid] / m;
        __syncthreads();
    }
    if (tid == 0) {
        float bv = v[0]; int last = 0;
        for (int j = 1; j < KNN; j++) if (v[j] > bv) { bv = v[j]; last = j; }
        path[TT - 1] = last;
        int idx = last;
        for (int t = TT - 2; t >= 0; t--) { idx = bp[t][idx]; path[t] = idx; }
    }
    __syncthreads();
    for (int n = tid; n < TT * D; n += 128) {
        int t = n / D, d2 = n % D;
        int row = g_idx[(b * TT + t) * KNN + path[t]];
        out[(size_t)(b * TT + t) * D + d2] = Tg[(size_t)row * D + d2];
    }
}

// ---------------- launch ----------------
extern "C" void kernel_launch(void* const* d_in, const int* in_sizes, int n_in,
                              void* d_out, int out_size) {
    (void)in_sizes; (void)n_in; (void)out_size;
    const float* Q  = (const float*)d_in[0];
    const float* Tg = (const float*)d_in[1];
    float* out = (float*)d_out;

    const int trans_smem  = (2 * D * KNN + 2 * KNN) * (int)sizeof(float);  // 103200 B
    const int select_smem = 131072;
    cudaFuncSetAttribute(trans_kernel, cudaFuncAttributeMaxDynamicSharedMemorySize, trans_smem);
    cudaFuncSetAttribute(select_kernel, cudaFuncAttributeMaxDynamicSharedMemorySize, select_smem);

    norms_kernel<<<(M + NQ + 255) / 256, 256>>>(Q, Tg);
    dist_kernel<<<dim3((M + 127) / 128, NQ / 128), 256>>>(Q, Tg);
    select_kernel<<<NQ, 256, select_smem>>>();
    gather_states_kernel<<<(NQ * KNN * (D / 4) + 255) / 256, 256>>>(Tg);
    trans_kernel<<<BB * (TT - 1), 256, trans_smem>>>();
    viterbi_kernel<<<BB, 128>>>(Tg, out);
}

// round 3
// speedup vs baseline: 2.1052x; 1.3215x over previous
#include <cuda_runtime.h>
#include <cstdint>

#define M    100000
#define NQ   256
#define D    128
#define KNN  100
#define BB   4
#define TT   64
#define CH   8
#define CHSZ (M / CH)     // 12500
#define CAPP 1024         // per-chunk candidate capacity

// ---------------- device scratch (no allocs allowed) ----------------
static __device__ float        g_qn[NQ];
static __device__ float        g_tn[M];
static __device__ unsigned int g_key[(size_t)NQ * M];               // 102.4 MB sortable keys
static __device__ unsigned long long g_part[NQ * CH * KNN];         // 1.6 MB chunk winners
static __device__ int          g_idx[NQ * KNN];
static __device__ float        g_emit[NQ * KNN];
static __device__ float        g_states[(size_t)NQ * KNN * D];
static __device__ float        g_trans[(size_t)BB * (TT - 1) * KNN * KNN];

__device__ __forceinline__ unsigned int f2key(float f) {
    unsigned int u = __float_as_uint(f);
    return (u & 0x80000000u) ? ~u : (u | 0x80000000u);
}
__device__ __forceinline__ float key2f(unsigned int k) {
    unsigned int u = (k & 0x80000000u) ? (k & 0x7fffffffu) : ~k;
    return __uint_as_float(u);
}

// ---------------- norms ----------------
__global__ void norms_kernel(const float* __restrict__ Q, const float* __restrict__ Tg) {
    int i = blockIdx.x * blockDim.x + threadIdx.x;
    if (i < M) {
        const float4* p = (const float4*)(Tg + (size_t)i * D);
        float acc = 0.f;
#pragma unroll
        for (int k = 0; k < D / 4; k++) {
            float4 v = p[k];
            acc += v.x * v.x + v.y * v.y + v.z * v.z + v.w * v.w;
        }
        g_tn[i] = acc;
    } else if (i < M + NQ) {
        int q = i - M;
        const float4* p = (const float4*)(Q + (size_t)q * D);
        float acc = 0.f;
#pragma unroll
        for (int k = 0; k < D / 4; k++) {
            float4 v = p[k];
            acc += v.x * v.x + v.y * v.y + v.z * v.z + v.w * v.w;
        }
        g_qn[q] = acc;
    }
}

// ---------------- distance GEMM -> sortable keys ----------------
__global__ __launch_bounds__(256, 2)
void dist_kernel(const float* __restrict__ Q, const float* __restrict__ Tg) {
    __shared__ __align__(16) float Qs[16][132];
    __shared__ __align__(16) float Ts[16][132];
    int tid = threadIdx.x;
    int tx = tid & 15, ty = tid >> 4;
    int q0 = blockIdx.y * 128, t0 = blockIdx.x * 128;
    int lr = tid >> 1;
    int lc = (tid & 1) * 8;
    const float* qbase = Q + (size_t)(q0 + lr) * D + lc;
    bool tvalid = (t0 + lr) < M;
    const float* tbase = Tg + (size_t)(tvalid ? (t0 + lr) : 0) * D + lc;

    float acc[8][8] = {};
    for (int k0 = 0; k0 < D; k0 += 16) {
        float4 qa = *(const float4*)(qbase + k0);
        float4 qb = *(const float4*)(qbase + k0 + 4);
        float4 ta = make_float4(0.f, 0.f, 0.f, 0.f), tb = ta;
        if (tvalid) {
            ta = *(const float4*)(tbase + k0);
            tb = *(const float4*)(tbase + k0 + 4);
        }
        Qs[lc + 0][lr] = qa.x; Qs[lc + 1][lr] = qa.y; Qs[lc + 2][lr] = qa.z; Qs[lc + 3][lr] = qa.w;
        Qs[lc + 4][lr] = qb.x; Qs[lc + 5][lr] = qb.y; Qs[lc + 6][lr] = qb.z; Qs[lc + 7][lr] = qb.w;
        Ts[lc + 0][lr] = ta.x; Ts[lc + 1][lr] = ta.y; Ts[lc + 2][lr] = ta.z; Ts[lc + 3][lr] = ta.w;
        Ts[lc + 4][lr] = tb.x; Ts[lc + 5][lr] = tb.y; Ts[lc + 6][lr] = tb.z; Ts[lc + 7][lr] = tb.w;
        __syncthreads();
#pragma unroll
        for (int k = 0; k < 16; k++) {
            float4 a0 = *(const float4*)&Qs[k][ty * 8];
            float4 a1 = *(const float4*)&Qs[k][ty * 8 + 4];
            float4 b0 = *(const float4*)&Ts[k][tx * 8];
            float4 b1 = *(const float4*)&Ts[k][tx * 8 + 4];
            float av[8] = {a0.x, a0.y, a0.z, a0.w, a1.x, a1.y, a1.z, a1.w};
            float bv[8] = {b0.x, b0.y, b0.z, b0.w, b1.x, b1.y, b1.z, b1.w};
#pragma unroll
            for (int ii = 0; ii < 8; ii++)
#pragma unroll
                for (int jj = 0; jj < 8; jj++)
                    acc[ii][jj] += av[ii] * bv[jj];
        }
        __syncthreads();
    }

    int tcol = t0 + tx * 8;
    float tn[8];
    bool v0 = (tcol + 3) < M, v1 = (tcol + 7) < M;
#pragma unroll
    for (int jj = 0; jj < 8; jj++)
        tn[jj] = ((jj < 4) ? v0 : v1) ? g_tn[tcol + jj] : 0.f;
#pragma unroll
    for (int ii = 0; ii < 8; ii++) {
        int q = q0 + ty * 8 + ii;
        float qn = g_qn[q];
        unsigned int keys[8];
#pragma unroll
        for (int jj = 0; jj < 8; jj++) {
            float s = qn + tn[jj];
            keys[jj] = f2key(s - 2.f * acc[ii][jj]);
        }
        unsigned int* dst = g_key + (size_t)q * M + tcol;
        if (v0) *(uint4*)dst = make_uint4(keys[0], keys[1], keys[2], keys[3]);
        if (v1) *(uint4*)(dst + 4) = make_uint4(keys[4], keys[5], keys[6], keys[7]);
    }
}

// ---------------- per-chunk exact top-K (smem-resident radix select) ----------------
// grid: (CH, NQ), 256 threads. Each block: one 12500-key chunk of one query row.
__global__ void select_part_kernel() {
    extern __shared__ __align__(16) unsigned int sp[];
    unsigned int* skey = sp;                                   // 12500 u32
    unsigned int* hist = sp + CHSZ;                            // 2048 u32
    unsigned long long* buf = (unsigned long long*)(sp + CHSZ + 2048);  // CAPP u64
    __shared__ unsigned int scanbuf[256];
    __shared__ unsigned int s_prefix, s_cnt;
    __shared__ int s_kneed;

    int q = blockIdx.y;
    int c0 = blockIdx.x * CHSZ;
    int tid = threadIdx.x;
    const unsigned int* krow = g_key + (size_t)q * M + c0;

    // load chunk into smem (uint4, 3125 vectors)
    for (int j = tid; j < CHSZ / 4; j += 256)
        *(uint4*)&skey[j * 4] = *(const uint4*)&krow[j * 4];
    if (tid == 0) { s_prefix = 0u; s_kneed = KNN; s_cnt = 0u; }
    __syncthreads();

    const int shifts[3]  = {21, 10, 0};
    const int bitsArr[3] = {11, 11, 10};
    for (int p = 0; p < 3; p++) {
        int shift = shifts[p];
        int nb = 1 << bitsArr[p];
        for (int i = tid; i < nb; i += 256) hist[i] = 0u;
        __syncthreads();
        unsigned int prefix = s_prefix;
        int top = shift + bitsArr[p];
        for (int j = tid; j < CHSZ; j += 256) {
            unsigned int key = skey[j];
            bool ok = (top >= 32) || ((key >> top) == (prefix >> top));
            if (ok) {
                unsigned int bin = (key >> shift) & (unsigned int)(nb - 1);
                unsigned int mm = __match_any_sync(__activemask(), bin);
                if ((int)(tid & 31) == __ffs(mm) - 1) atomicAdd(&hist[bin], (unsigned)__popc(mm));
            }
        }
        __syncthreads();
        int chunk = nb / 256;
        unsigned int ssum = 0u;
        for (int i = 0; i < chunk; i++) ssum += hist[tid * chunk + i];
        scanbuf[tid] = ssum;
        __syncthreads();
        for (int off = 1; off < 256; off <<= 1) {
            unsigned int a = scanbuf[tid];
            unsigned int b = (tid >= off) ? scanbuf[tid - off] : 0u;
            __syncthreads();
            scanbuf[tid] = a + b;
            __syncthreads();
        }
        int kneed = s_kneed;
        unsigned int excl = (tid == 0) ? 0u : scanbuf[tid - 1];
        unsigned int incl = scanbuf[tid];
        __syncthreads();
        if ((int)excl < kneed && kneed <= (int)incl) {
            unsigned int c = excl;
            for (int i = 0; i < chunk; i++) {
                unsigned int h = hist[tid * chunk + i];
                c += h;
                if (kneed <= (int)c) {
                    s_prefix = prefix | ((unsigned int)(tid * chunk + i) << shift);
                    s_kneed = kneed - (int)(c - h);
                    break;
                }
            }
        }
        __syncthreads();
    }

    unsigned int kth = s_prefix;   // exact key of the 100th smallest in this chunk
    for (int j = tid; j < CHSZ; j += 256) {
        unsigned int key = skey[j];
        if (key <= kth) {
            unsigned int pos = atomicAdd(&s_cnt, 1u);
            if (pos < CAPP)
                buf[pos] = ((unsigned long long)key << 32) | (unsigned int)(c0 + j);
        }
    }
    __syncthreads();
    int n = (int)s_cnt; if (n > CAPP) n = CAPP;
    int size = 128;
    while (size < n) size <<= 1;
    for (int i = tid; i < size; i += 256)
        if (i >= n) buf[i] = 0xFFFFFFFFFFFFFFFFull;
    __syncthreads();

    for (int k2 = 2; k2 <= size; k2 <<= 1) {
        for (int j2 = k2 >> 1; j2 > 0; j2 >>= 1) {
            for (int i = tid; i < size; i += 256) {
                int l = i ^ j2;
                if (l > i) {
                    unsigned long long a = buf[i], b = buf[l];
                    bool up = ((i & k2) == 0);
                    if ((a > b) == up) { buf[i] = b; buf[l] = a; }
                }
            }
            __syncthreads();
        }
    }

    unsigned long long* dst = g_part + (q * CH + blockIdx.x) * KNN;
    if (tid < KNN) dst[tid] = buf[tid];
}

// ---------------- merge 8x100 chunk winners -> global top-100 ----------------
__global__ void select_merge_kernel() {
    __shared__ unsigned long long buf[1024];
    __shared__ float sred[256];
    __shared__ float s_dmin;
    int q = blockIdx.x;
    int tid = threadIdx.x;
    const unsigned long long* src = g_part + q * CH * KNN;
    for (int i = tid; i < 1024; i += 256)
        buf[i] = (i < CH * KNN) ? src[i] : 0xFFFFFFFFFFFFFFFFull;
    __syncthreads();
    for (int k2 = 2; k2 <= 1024; k2 <<= 1) {
        for (int j2 = k2 >> 1; j2 > 0; j2 >>= 1) {
            for (int i = tid; i < 1024; i += 256) {
                int l = i ^ j2;
                if (l > i) {
                    unsigned long long a = buf[i], b = buf[l];
                    bool up = ((i & k2) == 0);
                    if ((a > b) == up) { buf[i] = b; buf[l] = a; }
                }
            }
            __syncthreads();
        }
    }
    if (tid == 0) s_dmin = key2f((unsigned int)(buf[0] >> 32));
    __syncthreads();
    float dmin = s_dmin;
    float myex = 0.f; int myidx = 0;
    if (tid < KNN) {
        unsigned long long e = buf[tid];
        myidx = (int)(unsigned int)(e & 0xffffffffull);
        float d = key2f((unsigned int)(e >> 32));
        myex = expf(dmin - d);
    }
    sred[tid] = (tid < KNN) ? myex : 0.f;
    __syncthreads();
    for (int off = 128; off > 0; off >>= 1) {
        if (tid < off) sred[tid] += sred[tid + off];
        __syncthreads();
    }
    float ssum = sred[0];
    if (tid < KNN) {
        g_emit[q * KNN + tid] = myex / ssum;
        g_idx[q * KNN + tid] = myidx;
    }
}

// ---------------- states gather ----------------
__global__ void gather_states_kernel(const float* __restrict__ Tg) {
    int n = blockIdx.x * blockDim.x + threadIdx.x;
    if (n >= NQ * KNN * (D / 4)) return;
    int row = n / (D / 4);
    int c = n % (D / 4);
    int tgt = g_idx[row];
    float4 v = *(const float4*)&Tg[(size_t)tgt * D + c * 4];
    *(float4*)&g_states[(size_t)row * D + c * 4] = v;
}

// ---------------- transitions: exp(-||a_i - b_j||^2) ----------------
__global__ void trans_kernel() {
    extern __shared__ __align__(16) float s[];
    float* sA = s;
    float* sB = s + D * KNN;
    float* an = s + 2 * D * KNN;
    float* bn = an + KNN;
    int bt = blockIdx.x;
    int b = bt / (TT - 1), tl = bt % (TT - 1);
    int qA = b * TT + tl, qB = qA + 1;
    for (int n = threadIdx.x; n < KNN * D; n += blockDim.x) {
        int i = n / D, k = n % D;
        sA[k * KNN + i] = g_states[(size_t)qA * KNN * D + n];
        sB[k * KNN + i] = g_states[(size_t)qB * KNN * D + n];
    }
    __syncthreads();
    for (int i = threadIdx.x; i < 2 * KNN; i += blockDim.x) {
        int ii = (i < KNN) ? i : (i - KNN);
        const float* sp = (i < KNN) ? sA : sB;
        float acc = 0.f;
        for (int k = 0; k < D; k++) { float x = sp[k * KNN + ii]; acc += x * x; }
        if (i < KNN) an[ii] = acc; else bn[ii] = acc;
    }
    __syncthreads();
    float* trow = g_trans + (size_t)bt * KNN * KNN;
    for (int t4 = threadIdx.x; t4 < 625; t4 += blockDim.x) {
        int i0 = (t4 / 25) * 4, j0 = (t4 % 25) * 4;
        float acc[4][4] = {};
        for (int k = 0; k < D; k++) {
            float4 a  = *(const float4*)&sA[k * KNN + i0];
            float4 b4 = *(const float4*)&sB[k * KNN + j0];
            acc[0][0] += a.x * b4.x; acc[0][1] += a.x * b4.y; acc[0][2] += a.x * b4.z; acc[0][3] += a.x * b4.w;
            acc[1][0] += a.y * b4.x; acc[1][1] += a.y * b4.y; acc[1][2] += a.y * b4.z; acc[1][3] += a.y * b4.w;
            acc[2][0] += a.z * b4.x; acc[2][1] += a.z * b4.y; acc[2][2] += a.z * b4.z; acc[2][3] += a.z * b4.w;
            acc[3][0] += a.w * b4.x; acc[3][1] += a.w * b4.y; acc[3][2] += a.w * b4.z; acc[3][3] += a.w * b4.w;
        }
#pragma unroll
        for (int ii = 0; ii < 4; ii++)
#pragma unroll
            for (int jj = 0; jj < 4; jj++) {
                int i = i0 + ii, j = j0 + jj;
                float dd = an[i] + bn[j] - 2.f * acc[ii][jj];
                trow[i * KNN + j] = expf(-dd);
            }
    }
}

// ---------------- viterbi (512 threads, i-loop split 4-way) ----------------
__global__ void viterbi_kernel(const float* __restrict__ Tg, float* __restrict__ out) {
    int b = blockIdx.x;
    int tid = threadIdx.x;            // 512
    int j = tid & 127, s = tid >> 7;  // s in 0..3
    __shared__ float v[128];
    __shared__ float part[4][128];
    __shared__ unsigned char parti[4][128];
    __shared__ float red[128];
    __shared__ unsigned char bp[TT - 1][KNN];
    __shared__ int path[TT];
    if (s == 0) v[j] = (j < KNN) ? g_emit[(b * TT) * KNN + j] : 0.f;
    __syncthreads();
    for (int t = 1; t < TT; t++) {
        const float* tr = g_trans + (size_t)(b * (TT - 1) + t - 1) * KNN * KNN;
        float best = -1.f; int back = 0;
        if (j < KNN) {
            int i0 = s * 25;
#pragma unroll
            for (int ii = 0; ii < 25; ii++) {
                int i = i0 + ii;
                float sc = v[i] * tr[i * KNN + j];
                if (sc > best) { best = sc; back = i; }
            }
        }
        part[s][j] = best; parti[s][j] = (unsigned char)back;
        __syncthreads();
        if (s == 0) {
            float em = (j < KNN) ? g_emit[(b * TT + t) * KNN + j] : 0.f;
            float bb = part[0][j]; int bk = parti[0][j];
#pragma unroll
            for (int ss = 1; ss < 4; ss++)
                if (part[ss][j] > bb) { bb = part[ss][j]; bk = parti[ss][j]; }
            if (j < KNN) bp[t - 1][j] = (unsigned char)bk;
            float vn = (j < KNN) ? bb * em : 0.f;
            red[j] = vn;
            part[0][j] = vn;  // stash
        }
        __syncthreads();
        for (int off = 64; off > 0; off >>= 1) {
            if (tid < off) red[tid] = fmaxf(red[tid], red[tid + off]);
            __syncthreads();
        }
        float m = fmaxf(red[0], 1e-30f);
        __syncthreads();
        if (s == 0) v[j] = part[0][j] / m;
        __syncthreads();
    }
    if (tid == 0) {
        float bv = v[0]; int last = 0;
        for (int jj = 1; jj < KNN; jj++) if (v[jj] > bv) { bv = v[jj]; last = jj; }
        path[TT - 1] = last;
        int idx = last;
        for (int t = TT - 2; t >= 0; t--) { idx = bp[t][idx]; path[t] = idx; }
    }
    __syncthreads();
    for (int n = tid; n < TT * D; n += 512) {
        int t = n / D, d2 = n % D;
        int row = g_idx[(b * TT + t) * KNN + path[t]];
        out[(size_t)(b * TT + t) * D + d2] = Tg[(size_t)row * D + d2];
    }
}

// ---------------- launch ----------------
extern "C" void kernel_launch(void* const* d_in, const int* in_sizes, int n_in,
                              void* d_out, int out_size) {
    (void)in_sizes; (void)n_in; (void)out_size;
    const float* Q  = (const float*)d_in[0];
    const float* Tg = (const float*)d_in[1];
    float* out = (float*)d_out;

    const int trans_smem = (2 * D * KNN + 2 * KNN) * (int)sizeof(float);       // 103200 B
    const int part_smem  = (CHSZ + 2048) * (int)sizeof(unsigned int) + CAPP * 8; // 66384 B
    cudaFuncSetAttribute(trans_kernel, cudaFuncAttributeMaxDynamicSharedMemorySize, trans_smem);
    cudaFuncSetAttribute(select_part_kernel, cudaFuncAttributeMaxDynamicSharedMemorySize, part_smem);

    norms_kernel<<<(M + NQ + 255) / 256, 256>>>(Q, Tg);
    dist_kernel<<<dim3((M + 127) / 128, NQ / 128), 256>>>(Q, Tg);
    select_part_kernel<<<dim3(CH, NQ), 256, part_smem>>>();
    select_merge_kernel<<<NQ, 256>>>();
    gather_states_kernel<<<(NQ * KNN * (D / 4) + 255) / 256, 256>>>(Tg);
    trans_kernel<<<BB * (TT - 1), 256, trans_smem>>>();
    viterbi_kernel<<<BB, 512>>>(Tg, out);
}